// round 8
// baseline (speedup 1.0000x reference)
#include <cuda_runtime.h>
#include <math.h>

// ---------------- scratch (device globals; no allocation allowed) ----------
__device__ float g_s1[128 * 20 * 24 * 24];   // adder1 out [B,20,24,24]
__device__ float g_s2[128 * 50 * 8 * 8];     // adder2 out [B,50,8,8]
__device__ float g_h[128 * 500];             // fc1 activations
__device__ float g_w2p[50 * 20 * 28];        // padded w2 [oc][c][28] (16B aligned rows)

__device__ float g_bsum1[20 * 128], g_bsq1[20 * 128];
__device__ float g_bsum2[50 * 128], g_bsq2[50 * 128];

// ---------------- adder1: [B,1,28,28] -> [B,20,24,24] + BN partials --------
// block = batch b, 960 threads = (oc 0..19) x (ph 0..23) x (half 0..1)
// also cooperatively repacks w2 into g_w2p (each block does a 196-elem slice)
__global__ __launch_bounds__(960) void adder1_k(const float* __restrict__ x,
                                                const float* __restrict__ w1,
                                                const float* __restrict__ w2) {
    __shared__ __align__(16) float xs[784];      // 28x28
    __shared__ float ws[500];                    // 20x25
    __shared__ float red_s[960], red_q[960];

    const int b = blockIdx.x;
    const int tid = threadIdx.x;

    // w2 repack slice: 128 blocks x 196 >= 25000
    {
        const int base = b * 196;
        for (int j = tid; j < 196; j += 960) {
            const int i = base + j;
            if (i < 25000) {
                const int oc = i / 500;
                const int r  = i % 500;
                const int c  = r / 25;
                const int k  = r % 25;
                g_w2p[oc * 560 + c * 28 + k] = w2[i];
            }
        }
    }

    for (int i = tid; i < 784; i += 960) xs[i] = x[b * 784 + i];
    for (int i = tid; i < 500; i += 960) ws[i] = w1[i];
    __syncthreads();

    const int oc   = tid / 48;
    const int r    = tid % 48;
    const int ph   = r / 2;
    const int half = r % 2;          // pw block: half*12 .. half*12+11

    float acc[12];
#pragma unroll
    for (int p = 0; p < 12; p++) acc[p] = 0.f;

#pragma unroll
    for (int kh = 0; kh < 5; kh++) {
        const float4* xrow = (const float4*)(xs + (ph + kh) * 28 + half * 12);
        float xr[16];
        float4 v0 = xrow[0], v1 = xrow[1], v2 = xrow[2], v3 = xrow[3];
        xr[0]=v0.x; xr[1]=v0.y; xr[2]=v0.z; xr[3]=v0.w;
        xr[4]=v1.x; xr[5]=v1.y; xr[6]=v1.z; xr[7]=v1.w;
        xr[8]=v2.x; xr[9]=v2.y; xr[10]=v2.z; xr[11]=v2.w;
        xr[12]=v3.x; xr[13]=v3.y; xr[14]=v3.z; xr[15]=v3.w;
#pragma unroll
        for (int kw = 0; kw < 5; kw++) {
            const float w = ws[oc * 25 + kh * 5 + kw];   // LDS broadcast
#pragma unroll
            for (int p = 0; p < 12; p++) acc[p] -= fabsf(xr[p + kw] - w);
        }
    }

    float lsum = 0.f, lsq = 0.f;
    float* outp = g_s1 + ((b * 20 + oc) * 24 + ph) * 24 + half * 12;
#pragma unroll
    for (int p = 0; p < 12; p++) {
        outp[p] = acc[p];
        lsum += acc[p];
        lsq  += acc[p] * acc[p];
    }
    red_s[tid] = lsum;
    red_q[tid] = lsq;
    __syncthreads();

    if (r == 0) {   // 20 threads, each sums its channel's 48 partials (deterministic)
        float s = 0.f, q = 0.f;
        for (int t = 0; t < 48; t++) { s += red_s[oc * 48 + t]; q += red_q[oc * 48 + t]; }
        g_bsum1[oc * 128 + b] = s;
        g_bsq1[oc * 128 + b]  = q;
    }
}

// ---------------- adder2 (bn1-params + bn1+pool fused): -> [B,50,8,8] ------
// block = batch b, 800 threads = (oc 0..49) x (ph 0..7) x (half 0..1)
__global__ __launch_bounds__(800) void adder2_k(const float* __restrict__ gamma1,
                                                const float* __restrict__ beta1) {
    __shared__ __align__(16) float xs[2880];   // pooled input 20x12x12
    __shared__ float red_s[800], red_q[800];
    __shared__ float s1s[20], s1b[20];

    const int b = blockIdx.x;
    const int tid = threadIdx.x;
    const int wid  = tid / 32;
    const int lane = tid % 32;

    // fused bnparam1: warp per channel (redundant per block, deterministic)
    if (wid < 20) {
        float s = 0.f, q = 0.f;
#pragma unroll
        for (int i = 0; i < 4; i++) {
            const int bb = lane + 32 * i;
            s += g_bsum1[wid * 128 + bb];
            q += g_bsq1[wid * 128 + bb];
        }
#pragma unroll
        for (int d = 16; d; d >>= 1) {
            s += __shfl_xor_sync(0xffffffffu, s, d);
            q += __shfl_xor_sync(0xffffffffu, q, d);
        }
        if (lane == 0) {
            const float invN = 1.f / (128.f * 24.f * 24.f);
            float m = s * invN;
            float v = q * invN - m * m;
            float sc = gamma1[wid] * rsqrtf(v + 1e-5f);
            s1s[wid] = sc;
            s1b[wid] = beta1[wid] - m * sc;
        }
    }
    __syncthreads();

    // fused bn1 + 2x2 maxpool from g_s1
    for (int i = tid; i < 2880; i += 800) {
        const int c   = i / 144;
        const int rem = i % 144;
        const int ph2 = rem / 12;
        const int pw2 = rem % 12;
        const float* base = g_s1 + ((b * 20 + c) * 24 + ph2 * 2) * 24 + pw2 * 2;
        const float s = s1s[c], be = s1b[c];
        float a0 = base[0]  * s + be;
        float a1 = base[1]  * s + be;
        float a2 = base[24] * s + be;
        float a3 = base[25] * s + be;
        xs[i] = fmaxf(fmaxf(a0, a1), fmaxf(a2, a3));
    }
    __syncthreads();

    const int oc   = tid / 16;
    const int sub  = tid % 16;
    const int ph   = sub / 2;
    const int half = sub % 2;     // pw block: half*4 .. half*4+3

    float acc[4];
#pragma unroll
    for (int p = 0; p < 4; p++) acc[p] = 0.f;

    const float4* wbase = (const float4*)(g_w2p + oc * 560);

    for (int c = 0; c < 20; c++) {
        // 7 x LDG.128 weight loads (padded, aligned)
        float wv[28];
        const float4* wp4 = wbase + c * 7;
#pragma unroll
        for (int q = 0; q < 7; q++) {
            float4 t = wp4[q];
            wv[q*4+0] = t.x; wv[q*4+1] = t.y; wv[q*4+2] = t.z; wv[q*4+3] = t.w;
        }
        const float* xc = xs + c * 144;
#pragma unroll
        for (int kh = 0; kh < 5; kh++) {
            const float4* xrow = (const float4*)(xc + (ph + kh) * 12 + half * 4);
            float4 v0 = xrow[0], v1 = xrow[1];
            float xr[8];
            xr[0]=v0.x; xr[1]=v0.y; xr[2]=v0.z; xr[3]=v0.w;
            xr[4]=v1.x; xr[5]=v1.y; xr[6]=v1.z; xr[7]=v1.w;
#pragma unroll
            for (int kw = 0; kw < 5; kw++) {
                const float w = wv[kh * 5 + kw];
#pragma unroll
                for (int p = 0; p < 4; p++) acc[p] -= fabsf(xr[p + kw] - w);
            }
        }
    }

    float lsum = 0.f, lsq = 0.f;
    float* op = g_s2 + ((b * 50 + oc) * 8 + ph) * 8 + half * 4;
#pragma unroll
    for (int p = 0; p < 4; p++) {
        op[p] = acc[p];
        lsum += acc[p];
        lsq  += acc[p] * acc[p];
    }
    red_s[tid] = lsum;
    red_q[tid] = lsq;
    __syncthreads();

    if (sub == 0) {   // 50 threads, 16 partials each (deterministic)
        float s = 0.f, q = 0.f;
        for (int t = 0; t < 16; t++) { s += red_s[oc * 16 + t]; q += red_q[oc * 16 + t]; }
        g_bsum2[oc * 128 + b] = s;
        g_bsq2[oc * 128 + b]  = q;
    }
}

// ---------------- fc1 (bn2-params + bn2+pool fused): 4 batches x 125 outs --
// grid = 32 batch-groups x 4 output-quarters = 128 blocks, 512 threads
__global__ __launch_bounds__(512) void fc1_k(const float* __restrict__ fc1_w,
                                             const float* __restrict__ fc1_b,
                                             const float* __restrict__ gamma2,
                                             const float* __restrict__ beta2) {
    __shared__ __align__(16) float p_s[4][800];
    __shared__ float s2s[50], s2b[50];

    const int bg = blockIdx.x >> 2;      // 0..31
    const int oq = blockIdx.x & 3;       // 0..3
    const int b0 = bg * 4;
    const int tid = threadIdx.x;
    const int wid  = tid / 32;
    const int lane = tid % 32;

    // fused bnparam2: 16 warps cover 50 channels (redundant per block)
    for (int c = wid; c < 50; c += 16) {
        float s = 0.f, q = 0.f;
#pragma unroll
        for (int i = 0; i < 4; i++) {
            const int bb = lane + 32 * i;
            s += g_bsum2[c * 128 + bb];
            q += g_bsq2[c * 128 + bb];
        }
#pragma unroll
        for (int d = 16; d; d >>= 1) {
            s += __shfl_xor_sync(0xffffffffu, s, d);
            q += __shfl_xor_sync(0xffffffffu, q, d);
        }
        if (lane == 0) {
            const float invN = 1.f / (128.f * 8.f * 8.f);
            float m = s * invN;
            float v = q * invN - m * m;
            float sc = gamma2[c] * rsqrtf(v + 1e-5f);
            s2s[c] = sc;
            s2b[c] = beta2[c] - m * sc;
        }
    }
    __syncthreads();

    // bn2 + 2x2 maxpool -> flattened 800 per batch
    for (int i = tid; i < 3200; i += 512) {
        const int bb = i / 800;
        const int o  = i % 800;
        const int c   = o / 16;
        const int r   = (o % 16) / 4;
        const int col = o % 4;
        const float* base = g_s2 + (((b0 + bb) * 50 + c) * 8 + r * 2) * 8 + col * 2;
        const float s = s2s[c], be = s2b[c];
        float a0 = base[0] * s + be;
        float a1 = base[1] * s + be;
        float a2 = base[8] * s + be;
        float a3 = base[9] * s + be;
        p_s[bb][o] = fmaxf(fmaxf(a0, a1), fmaxf(a2, a3));
    }
    __syncthreads();

    // warp handles 8 outputs x 4 batches; x cached in registers across outputs
    int olist[8];
    const float4* wrow[8];
#pragma unroll
    for (int j = 0; j < 8; j++) {
        int idx = wid * 8 + j;
        bool valid = idx < 125;
        int o = oq * 125 + (valid ? idx : 0);
        olist[j] = valid ? o : -1;
        wrow[j] = (const float4*)(fc1_w + o * 800);
    }

    float acc[8][4];
#pragma unroll
    for (int j = 0; j < 8; j++)
#pragma unroll
        for (int bb = 0; bb < 4; bb++) acc[j][bb] = 0.f;

#pragma unroll
    for (int i = 0; i < 7; i++) {
        const int fidx = lane + 32 * i;          // float4 index, < 200
        const bool v = fidx < 200;
        float4 x4[4];
#pragma unroll
        for (int bb = 0; bb < 4; bb++)
            x4[bb] = v ? ((const float4*)p_s[bb])[fidx] : make_float4(0.f, 0.f, 0.f, 0.f);
#pragma unroll
        for (int j = 0; j < 8; j++) {
            float4 wv = v ? wrow[j][fidx] : make_float4(0.f, 0.f, 0.f, 0.f);
#pragma unroll
            for (int bb = 0; bb < 4; bb++) {
                acc[j][bb] = fmaf(wv.x, x4[bb].x, acc[j][bb]);
                acc[j][bb] = fmaf(wv.y, x4[bb].y, acc[j][bb]);
                acc[j][bb] = fmaf(wv.z, x4[bb].z, acc[j][bb]);
                acc[j][bb] = fmaf(wv.w, x4[bb].w, acc[j][bb]);
            }
        }
    }

#pragma unroll
    for (int j = 0; j < 8; j++) {
#pragma unroll
        for (int bb = 0; bb < 4; bb++) {
            float a = acc[j][bb];
#pragma unroll
            for (int d = 16; d; d >>= 1) a += __shfl_xor_sync(0xffffffffu, a, d);
            acc[j][bb] = a;
        }
        if (lane == 0 && olist[j] >= 0) {
            const float bia = fc1_b[olist[j]];
#pragma unroll
            for (int bb = 0; bb < 4; bb++)
                g_h[(b0 + bb) * 500 + olist[j]] = fmaxf(acc[j][bb] + bia, 0.f);
        }
    }
}

// ---------------- fc2 + softmax: one block per batch, 10 warps -------------
__global__ __launch_bounds__(320) void fc2soft_k(const float* __restrict__ fc2_w,
                                                 const float* __restrict__ fc2_b,
                                                 float* __restrict__ out) {
    __shared__ float logit_s[10];
    const int b = blockIdx.x;
    const int wid  = threadIdx.x / 32;
    const int lane = threadIdx.x % 32;

    float a = 0.f;
    const float* wr = fc2_w + wid * 500;
    const float* hr = g_h + b * 500;
#pragma unroll
    for (int i = 0; i < 16; i++) {
        int k = lane + 32 * i;
        if (k < 500) a = fmaf(wr[k], hr[k], a);
    }
#pragma unroll
    for (int d = 16; d; d >>= 1) a += __shfl_xor_sync(0xffffffffu, a, d);
    if (lane == 0) logit_s[wid] = a + fc2_b[wid];
    __syncthreads();

    if (threadIdx.x < 10) {
        const int j = threadIdx.x;
        float mx = -1e30f;
        for (int t = 0; t < 10; t++) mx = fmaxf(mx, logit_s[t]);
        float sum = 0.f;
        for (int t = 0; t < 10; t++) sum += expf(logit_s[t] - mx);
        out[b * 10 + j] = expf(logit_s[j] - mx) / sum;
    }
}

// ---------------- launch ----------------------------------------------------
extern "C" void kernel_launch(void* const* d_in, const int* in_sizes, int n_in,
                              void* d_out, int out_size) {
    const float* x      = (const float*)d_in[0];
    const float* w1     = (const float*)d_in[1];
    const float* gamma1 = (const float*)d_in[2];
    const float* beta1  = (const float*)d_in[3];
    const float* w2     = (const float*)d_in[4];
    const float* gamma2 = (const float*)d_in[5];
    const float* beta2  = (const float*)d_in[6];
    const float* fc1_w  = (const float*)d_in[7];
    const float* fc1_b  = (const float*)d_in[8];
    const float* fc2_w  = (const float*)d_in[9];
    const float* fc2_b  = (const float*)d_in[10];
    float* out = (float*)d_out;

    adder1_k<<<128, 960>>>(x, w1, w2);
    adder2_k<<<128, 800>>>(gamma1, beta1);
    fc1_k<<<128, 512>>>(fc1_w, fc1_b, gamma2, beta2);
    fc2soft_k<<<128, 320>>>(fc2_w, fc2_b, out);
}

// round 9
// speedup vs baseline: 1.0352x; 1.0352x over previous
#include <cuda_runtime.h>
#include <math.h>

// ---------------- scratch (device globals; no allocation allowed) ----------
__device__ float g_s1[128 * 20 * 24 * 24];   // adder1 out [B,20,24,24]
__device__ float g_s2[128 * 50 * 8 * 8];     // adder2 out [B,50,8,8]
__device__ float g_h[128 * 500];             // fc1 activations
__device__ float g_w2p[50 * 20 * 28];        // padded w2 [oc][c][28] (16B rows)

__device__ float g_bsum1[20 * 128], g_bsq1[20 * 128];
__device__ float g_bsum2[50 * 128], g_bsq2[50 * 128];

__device__ unsigned long long g_barctr = 0;  // monotonic epoch barrier counter

// grid-wide barrier: monotonic counter, safe across graph replays
__device__ __forceinline__ void grid_barrier() {
    __syncthreads();
    if (threadIdx.x == 0) {
        __threadfence();
        unsigned long long old = atomicAdd(&g_barctr, 1ULL);
        unsigned long long target = (old / gridDim.x + 1ULL) * (unsigned long long)gridDim.x;
        while (*((volatile unsigned long long*)&g_barctr) < target) { __nanosleep(64); }
        __threadfence();
    }
    __syncthreads();
}

// ---------------- shared memory union over stages ---------------------------
struct SA { float xs[784]; float ws[500]; float red_s[960]; float red_q[960]; };
struct SB { float xs[2880]; float red_s[800]; float red_q[800]; float s1s[20]; float s1b[20]; };
struct SC { float p_s[4][800]; float s2s[50]; float s2b[50]; };
struct SD { float logits[10]; };
union SU { SA a; SB b; SC c; SD d; };

// ---------------- mega kernel ----------------------------------------------
__global__ __launch_bounds__(1024, 1) void mega_k(
    const float* __restrict__ x,      const float* __restrict__ w1,
    const float* __restrict__ gamma1, const float* __restrict__ beta1,
    const float* __restrict__ w2,
    const float* __restrict__ gamma2, const float* __restrict__ beta2,
    const float* __restrict__ fc1_w,  const float* __restrict__ fc1_b,
    const float* __restrict__ fc2_w,  const float* __restrict__ fc2_b,
    float* __restrict__ out)
{
    __shared__ __align__(16) SU sm;

    const int blk  = blockIdx.x;        // 0..127
    const int tid  = threadIdx.x;
    const int wid  = tid / 32;
    const int lane = tid % 32;

    // ======================= STAGE A: adder1 (+ w2 repack) =================
    {
        const int b = blk;
        // w2 repack slice: 128 blocks x 196 >= 25000
        {
            const int i = b * 196 + tid;
            if (tid < 196 && i < 25000) {
                const int oc = i / 500;
                const int r  = i % 500;
                g_w2p[oc * 560 + (r / 25) * 28 + (r % 25)] = w2[i];
            }
        }
        for (int i = tid; i < 784; i += 1024) sm.a.xs[i] = x[b * 784 + i];
        for (int i = tid; i < 500; i += 1024) sm.a.ws[i] = w1[i];
        __syncthreads();

        if (tid < 960) {
            const int oc   = tid / 48;
            const int r    = tid % 48;
            const int ph   = r / 2;
            const int half = r % 2;

            float acc[12];
#pragma unroll
            for (int p = 0; p < 12; p++) acc[p] = 0.f;

#pragma unroll
            for (int kh = 0; kh < 5; kh++) {
                const float4* xrow = (const float4*)(sm.a.xs + (ph + kh) * 28 + half * 12);
                float xr[16];
                float4 v0 = xrow[0], v1 = xrow[1], v2 = xrow[2], v3 = xrow[3];
                xr[0]=v0.x; xr[1]=v0.y; xr[2]=v0.z; xr[3]=v0.w;
                xr[4]=v1.x; xr[5]=v1.y; xr[6]=v1.z; xr[7]=v1.w;
                xr[8]=v2.x; xr[9]=v2.y; xr[10]=v2.z; xr[11]=v2.w;
                xr[12]=v3.x; xr[13]=v3.y; xr[14]=v3.z; xr[15]=v3.w;
#pragma unroll
                for (int kw = 0; kw < 5; kw++) {
                    const float w = sm.a.ws[oc * 25 + kh * 5 + kw];
#pragma unroll
                    for (int p = 0; p < 12; p++) {
                        float d = fmaf(w, -1.0f, xr[p + kw]);          // FFMA-imm
                        acc[p]  = fmaf(fabsf(d), -1.0f, acc[p]);       // FFMA-imm
                    }
                }
            }

            float lsum = 0.f, lsq = 0.f;
            float* outp = g_s1 + ((b * 20 + oc) * 24 + ph) * 24 + half * 12;
#pragma unroll
            for (int p = 0; p < 12; p++) {
                outp[p] = acc[p];
                lsum += acc[p];
                lsq  += acc[p] * acc[p];
            }
            sm.a.red_s[tid] = lsum;
            sm.a.red_q[tid] = lsq;
        }
        __syncthreads();

        if (tid < 960 && (tid % 48) == 0) {   // 20 threads, deterministic
            const int oc = tid / 48;
            float s = 0.f, q = 0.f;
            for (int t = 0; t < 48; t++) { s += sm.a.red_s[oc * 48 + t]; q += sm.a.red_q[oc * 48 + t]; }
            g_bsum1[oc * 128 + b] = s;
            g_bsq1[oc * 128 + b]  = q;
        }
    }

    grid_barrier();

    // ======================= STAGE B: bn1+pool + adder2 =====================
    {
        const int b = blk;

        // bnparam1: warp per channel (redundant per block, deterministic)
        if (wid < 20) {
            float s = 0.f, q = 0.f;
#pragma unroll
            for (int i = 0; i < 4; i++) {
                const int bb = lane + 32 * i;
                s += g_bsum1[wid * 128 + bb];
                q += g_bsq1[wid * 128 + bb];
            }
#pragma unroll
            for (int d = 16; d; d >>= 1) {
                s += __shfl_xor_sync(0xffffffffu, s, d);
                q += __shfl_xor_sync(0xffffffffu, q, d);
            }
            if (lane == 0) {
                const float invN = 1.f / (128.f * 24.f * 24.f);
                float m = s * invN;
                float v = q * invN - m * m;
                float sc = gamma1[wid] * rsqrtf(v + 1e-5f);
                sm.b.s1s[wid] = sc;
                sm.b.s1b[wid] = beta1[wid] - m * sc;
            }
        }
        __syncthreads();

        for (int i = tid; i < 2880; i += 1024) {
            const int c   = i / 144;
            const int rem = i % 144;
            const int ph2 = rem / 12;
            const int pw2 = rem % 12;
            const float* base = g_s1 + ((b * 20 + c) * 24 + ph2 * 2) * 24 + pw2 * 2;
            const float s = sm.b.s1s[c], be = sm.b.s1b[c];
            float a0 = base[0]  * s + be;
            float a1 = base[1]  * s + be;
            float a2 = base[24] * s + be;
            float a3 = base[25] * s + be;
            sm.b.xs[i] = fmaxf(fmaxf(a0, a1), fmaxf(a2, a3));
        }
        __syncthreads();

        if (tid < 800) {
            const int oc   = tid / 16;
            const int sub  = tid % 16;
            const int ph   = sub / 2;
            const int half = sub % 2;

            float acc[4];
#pragma unroll
            for (int p = 0; p < 4; p++) acc[p] = 0.f;

            const float4* wbase = (const float4*)(g_w2p + oc * 560);

            for (int c = 0; c < 20; c++) {
                float wv[28];
                const float4* wp4 = wbase + c * 7;
#pragma unroll
                for (int q = 0; q < 7; q++) {
                    float4 t = wp4[q];
                    wv[q*4+0] = t.x; wv[q*4+1] = t.y; wv[q*4+2] = t.z; wv[q*4+3] = t.w;
                }
                const float* xc = sm.b.xs + c * 144;
#pragma unroll
                for (int kh = 0; kh < 5; kh++) {
                    const float4* xrow = (const float4*)(xc + (ph + kh) * 12 + half * 4);
                    float4 v0 = xrow[0], v1 = xrow[1];
                    float xr[8];
                    xr[0]=v0.x; xr[1]=v0.y; xr[2]=v0.z; xr[3]=v0.w;
                    xr[4]=v1.x; xr[5]=v1.y; xr[6]=v1.z; xr[7]=v1.w;
#pragma unroll
                    for (int kw = 0; kw < 5; kw++) {
                        const float w = wv[kh * 5 + kw];
#pragma unroll
                        for (int p = 0; p < 4; p++) {
                            float d = fmaf(w, -1.0f, xr[p + kw]);       // FFMA-imm
                            acc[p]  = fmaf(fabsf(d), -1.0f, acc[p]);    // FFMA-imm
                        }
                    }
                }
            }

            float lsum = 0.f, lsq = 0.f;
            float* op = g_s2 + ((b * 50 + oc) * 8 + ph) * 8 + half * 4;
#pragma unroll
            for (int p = 0; p < 4; p++) {
                op[p] = acc[p];
                lsum += acc[p];
                lsq  += acc[p] * acc[p];
            }
            sm.b.red_s[tid] = lsum;
            sm.b.red_q[tid] = lsq;
        }
        __syncthreads();

        if (tid < 800 && (tid % 16) == 0) {   // 50 threads, deterministic
            const int oc = tid / 16;
            float s = 0.f, q = 0.f;
            for (int t = 0; t < 16; t++) { s += sm.b.red_s[oc * 16 + t]; q += sm.b.red_q[oc * 16 + t]; }
            g_bsum2[oc * 128 + b] = s;
            g_bsq2[oc * 128 + b]  = q;
        }
    }

    grid_barrier();

    // ======================= STAGE C: bn2+pool + fc1 ========================
    {
        const int bg = blk >> 2;
        const int oq = blk & 3;
        const int b0 = bg * 4;

        // bnparam2: 32 warps cover 50 channels (redundant per block)
        for (int c = wid; c < 50; c += 32) {
            float s = 0.f, q = 0.f;
#pragma unroll
            for (int i = 0; i < 4; i++) {
                const int bb = lane + 32 * i;
                s += g_bsum2[c * 128 + bb];
                q += g_bsq2[c * 128 + bb];
            }
#pragma unroll
            for (int d = 16; d; d >>= 1) {
                s += __shfl_xor_sync(0xffffffffu, s, d);
                q += __shfl_xor_sync(0xffffffffu, q, d);
            }
            if (lane == 0) {
                const float invN = 1.f / (128.f * 8.f * 8.f);
                float m = s * invN;
                float v = q * invN - m * m;
                float sc = gamma2[c] * rsqrtf(v + 1e-5f);
                sm.c.s2s[c] = sc;
                sm.c.s2b[c] = beta2[c] - m * sc;
            }
        }
        __syncthreads();

        for (int i = tid; i < 3200; i += 1024) {
            const int bb = i / 800;
            const int o  = i % 800;
            const int c   = o / 16;
            const int r   = (o % 16) / 4;
            const int col = o % 4;
            const float* base = g_s2 + (((b0 + bb) * 50 + c) * 8 + r * 2) * 8 + col * 2;
            const float s = sm.c.s2s[c], be = sm.c.s2b[c];
            float a0 = base[0] * s + be;
            float a1 = base[1] * s + be;
            float a2 = base[8] * s + be;
            float a3 = base[9] * s + be;
            sm.c.p_s[bb][o] = fmaxf(fmaxf(a0, a1), fmaxf(a2, a3));
        }
        __syncthreads();

        // 32 warps x 4 outputs x 4 batches
        int olist[4];
        const float4* wrow[4];
#pragma unroll
        for (int j = 0; j < 4; j++) {
            int idx = wid * 4 + j;
            bool valid = idx < 125;
            int o = oq * 125 + (valid ? idx : 0);
            olist[j] = valid ? o : -1;
            wrow[j] = (const float4*)(fc1_w + o * 800);
        }

        float acc[4][4];
#pragma unroll
        for (int j = 0; j < 4; j++)
#pragma unroll
            for (int bb = 0; bb < 4; bb++) acc[j][bb] = 0.f;

#pragma unroll
        for (int i = 0; i < 7; i++) {
            const int fidx = lane + 32 * i;
            const bool v = fidx < 200;
            float4 x4[4];
#pragma unroll
            for (int bb = 0; bb < 4; bb++)
                x4[bb] = v ? ((const float4*)sm.c.p_s[bb])[fidx] : make_float4(0.f,0.f,0.f,0.f);
#pragma unroll
            for (int j = 0; j < 4; j++) {
                float4 wv = v ? wrow[j][fidx] : make_float4(0.f,0.f,0.f,0.f);
#pragma unroll
                for (int bb = 0; bb < 4; bb++) {
                    acc[j][bb] = fmaf(wv.x, x4[bb].x, acc[j][bb]);
                    acc[j][bb] = fmaf(wv.y, x4[bb].y, acc[j][bb]);
                    acc[j][bb] = fmaf(wv.z, x4[bb].z, acc[j][bb]);
                    acc[j][bb] = fmaf(wv.w, x4[bb].w, acc[j][bb]);
                }
            }
        }

#pragma unroll
        for (int j = 0; j < 4; j++) {
#pragma unroll
            for (int bb = 0; bb < 4; bb++) {
                float a = acc[j][bb];
#pragma unroll
                for (int d = 16; d; d >>= 1) a += __shfl_xor_sync(0xffffffffu, a, d);
                acc[j][bb] = a;
            }
            if (lane == 0 && olist[j] >= 0) {
                const float bia = fc1_b[olist[j]];
#pragma unroll
                for (int bb = 0; bb < 4; bb++)
                    g_h[(b0 + bb) * 500 + olist[j]] = fmaxf(acc[j][bb] + bia, 0.f);
            }
        }
    }

    grid_barrier();

    // ======================= STAGE D: fc2 + softmax =========================
    {
        const int b = blk;
        if (tid < 320) {
            float a = 0.f;
            const float* wr = fc2_w + wid * 500;
            const float* hr = g_h + b * 500;
#pragma unroll
            for (int i = 0; i < 16; i++) {
                int k = lane + 32 * i;
                if (k < 500) a = fmaf(wr[k], hr[k], a);
            }
#pragma unroll
            for (int d = 16; d; d >>= 1) a += __shfl_xor_sync(0xffffffffu, a, d);
            if (lane == 0) sm.d.logits[wid] = a + fc2_b[wid];
        }
        __syncthreads();

        if (tid < 10) {
            const int j = tid;
            float mx = -1e30f;
            for (int t = 0; t < 10; t++) mx = fmaxf(mx, sm.d.logits[t]);
            float sum = 0.f;
            for (int t = 0; t < 10; t++) sum += expf(sm.d.logits[t] - mx);
            out[b * 10 + j] = expf(sm.d.logits[j] - mx) / sum;
        }
    }
}

// ---------------- launch ----------------------------------------------------
extern "C" void kernel_launch(void* const* d_in, const int* in_sizes, int n_in,
                              void* d_out, int out_size) {
    const float* x      = (const float*)d_in[0];
    const float* w1     = (const float*)d_in[1];
    const float* gamma1 = (const float*)d_in[2];
    const float* beta1  = (const float*)d_in[3];
    const float* w2     = (const float*)d_in[4];
    const float* gamma2 = (const float*)d_in[5];
    const float* beta2  = (const float*)d_in[6];
    const float* fc1_w  = (const float*)d_in[7];
    const float* fc1_b  = (const float*)d_in[8];
    const float* fc2_w  = (const float*)d_in[9];
    const float* fc2_b  = (const float*)d_in[10];
    float* out = (float*)d_out;

    mega_k<<<128, 1024>>>(x, w1, gamma1, beta1, w2, gamma2, beta2,
                          fc1_w, fc1_b, fc2_w, fc2_b, out);
}